// round 5
// baseline (speedup 1.0000x reference)
#include <cuda_runtime.h>

#define B_ 8
#define S_ 2048
#define E_ 1024
#define H_ 64
#define M_ (B_*S_)          // 16384 rows for QKV projection
#define PAD 68              // smem row pitch (floats); 272B keeps 16B alignment

// Scratch for projected q,k,v: [B,S,H] each (4MB each). Device globals per harness rules.
__device__ float g_q[M_*H_];
__device__ float g_k[M_*H_];
__device__ float g_v[M_*H_];

// ---------------------------------------------------------------------------
// Kernel 1: fused QKV projection. out[m][h] = sum_k x[m][k]*w[k][h] + bias[h]
// Grid (M/64, 3); block 256 threads; 64x64 tile, BK=16, 4x4 per thread.
// ---------------------------------------------------------------------------
__global__ __launch_bounds__(256) void qkv_gemm_kernel(
    const float* __restrict__ x,
    const float* __restrict__ wq, const float* __restrict__ bq,
    const float* __restrict__ wk, const float* __restrict__ bk,
    const float* __restrict__ wv, const float* __restrict__ bv)
{
    __shared__ float As[16][PAD];   // x tile, transposed: As[k][m]
    __shared__ float Bs[16][64];    // w tile: Bs[k][h]

    const int mat = blockIdx.y;
    const float* __restrict__ w    = (mat==0) ? wq : ((mat==1) ? wk : wv);
    const float* __restrict__ bias = (mat==0) ? bq : ((mat==1) ? bk : bv);
    float* __restrict__ out        = (mat==0) ? g_q : ((mat==1) ? g_k : g_v);

    const int m0  = blockIdx.x * 64;
    const int tid = threadIdx.x;
    const int tx  = tid & 15;       // output h / 4
    const int ty  = tid >> 4;       // output m / 4
    const int lm  = tid >> 2;       // A-load row (0..63)
    const int lk  = (tid & 3) * 4;  // A-load k offset
    const int br  = tid >> 4;       // B-load k row (0..15)
    const int bh  = (tid & 15) * 4; // B-load h offset

    float acc[4][4] = {};

    for (int k0 = 0; k0 < E_; k0 += 16) {
        float4 av  = *(const float4*)(x + (size_t)(m0 + lm) * E_ + k0 + lk);
        float4 wv4 = *(const float4*)(w + (size_t)(k0 + br) * H_ + bh);
        __syncthreads();   // previous iteration's reads complete before overwrite
        As[lk+0][lm] = av.x; As[lk+1][lm] = av.y;
        As[lk+2][lm] = av.z; As[lk+3][lm] = av.w;
        *(float4*)&Bs[br][bh] = wv4;
        __syncthreads();
        #pragma unroll
        for (int kk = 0; kk < 16; kk++) {
            float4 a = *(float4*)&As[kk][ty*4];
            float4 b = *(float4*)&Bs[kk][tx*4];
            const float* ap = (const float*)&a;
            const float* bp = (const float*)&b;
            #pragma unroll
            for (int i = 0; i < 4; i++)
                #pragma unroll
                for (int j = 0; j < 4; j++)
                    acc[i][j] = fmaf(ap[i], bp[j], acc[i][j]);
        }
    }

    float4 bv4 = *(const float4*)(bias + tx*4);
    const float* bbp = (const float*)&bv4;
    #pragma unroll
    for (int i = 0; i < 4; i++) {
        float4 r;
        r.x = acc[i][0] + bbp[0];
        r.y = acc[i][1] + bbp[1];
        r.z = acc[i][2] + bbp[2];
        r.w = acc[i][3] + bbp[3];
        *(float4*)(out + (size_t)(m0 + ty*4 + i) * H_ + tx*4) = r;
    }
}

// ---------------------------------------------------------------------------
// Kernel 2: causal flash attention. One block per (batch, 64-query tile).
// 256 threads, 4x4 register blocking, 64-wide K tiles, online softmax.
// smem: Qt[h][q] (scaled), KPt[h][k] (reused as Pt[k][q]), Vs[k][h].
// ---------------------------------------------------------------------------
__global__ __launch_bounds__(256) void fa_kernel(float* __restrict__ Y)
{
    extern __shared__ float sm[];
    float* Qt  = sm;                 // [64][PAD]
    float* KPt = sm + 64 * PAD;      // [64][PAD]
    float* Vs  = sm + 2 * 64 * PAD;  // [64][PAD]

    const int b   = blockIdx.y;
    const int qt  = 31 - blockIdx.x;      // heavy tiles first
    const int tid = threadIdx.x;
    const int tx  = tid & 15;             // k (then h) / 4
    const int ty  = tid >> 4;             // q / 4
    const int lr  = tid >> 4;             // loader row (0..15)
    const int lh  = (tid & 15) * 4;       // loader h offset

    const float* __restrict__ Qb = g_q + ((size_t)b * S_ + qt * 64) * H_;
    const float* __restrict__ Kb = g_k + (size_t)b * S_ * H_;
    const float* __restrict__ Vb = g_v + (size_t)b * S_ * H_;

    // Load Q tile transposed, pre-scaled by 1/sqrt(64)
    #pragma unroll
    for (int p = 0; p < 4; p++) {
        int q = p * 16 + lr;
        float4 v = *(const float4*)(Qb + q * H_ + lh);
        Qt[(lh+0)*PAD + q] = v.x * 0.125f;
        Qt[(lh+1)*PAD + q] = v.y * 0.125f;
        Qt[(lh+2)*PAD + q] = v.z * 0.125f;
        Qt[(lh+3)*PAD + q] = v.w * 0.125f;
    }

    float mrow[4], lrow[4], o[4][4];
    #pragma unroll
    for (int i = 0; i < 4; i++) {
        mrow[i] = -1e30f; lrow[i] = 0.f;
        #pragma unroll
        for (int j = 0; j < 4; j++) o[i][j] = 0.f;
    }

    for (int kt = 0; kt <= qt; kt++) {
        __syncthreads();  // previous O-gemm reads of KPt/Vs complete
        #pragma unroll
        for (int p = 0; p < 4; p++) {
            int k = p * 16 + lr;
            const float* kr = Kb + (size_t)(kt * 64 + k) * H_;
            float4 kv = *(const float4*)(kr + lh);
            KPt[(lh+0)*PAD + k] = kv.x;
            KPt[(lh+1)*PAD + k] = kv.y;
            KPt[(lh+2)*PAD + k] = kv.z;
            KPt[(lh+3)*PAD + k] = kv.w;
            float4 vv = *(const float4*)(Vb + (size_t)(kt * 64 + k) * H_ + lh);
            *(float4*)&Vs[k*PAD + lh] = vv;
        }
        __syncthreads();

        // S = (Q*scale) @ K^T  (64x64x64)
        float s[4][4] = {};
        #pragma unroll
        for (int h = 0; h < 64; h++) {
            float4 a  = *(float4*)&Qt[h*PAD + ty*4];
            float4 bb = *(float4*)&KPt[h*PAD + tx*4];
            const float* ap = (const float*)&a;
            const float* bp = (const float*)&bb;
            #pragma unroll
            for (int i = 0; i < 4; i++)
                #pragma unroll
                for (int j = 0; j < 4; j++)
                    s[i][j] = fmaf(ap[i], bp[j], s[i][j]);
        }

        // Causal mask only on the diagonal tile
        if (kt == qt) {
            #pragma unroll
            for (int i = 0; i < 4; i++)
                #pragma unroll
                for (int j = 0; j < 4; j++)
                    if (tx*4 + j > ty*4 + i) s[i][j] = -1e30f;
        }

        // Online softmax per q row (row owned by 16 consecutive lanes)
        #pragma unroll
        for (int i = 0; i < 4; i++) {
            float mt = fmaxf(fmaxf(s[i][0], s[i][1]), fmaxf(s[i][2], s[i][3]));
            #pragma unroll
            for (int off = 8; off >= 1; off >>= 1)
                mt = fmaxf(mt, __shfl_xor_sync(0xffffffffu, mt, off));
            float mn   = fmaxf(mrow[i], mt);
            float corr = __expf(mrow[i] - mn);
            mrow[i] = mn;
            float ls = 0.f;
            #pragma unroll
            for (int j = 0; j < 4; j++) {
                s[i][j] = __expf(s[i][j] - mn);
                ls += s[i][j];
            }
            #pragma unroll
            for (int off = 8; off >= 1; off >>= 1)
                ls += __shfl_xor_sync(0xffffffffu, ls, off);
            lrow[i] = lrow[i] * corr + ls;
            #pragma unroll
            for (int j = 0; j < 4; j++) o[i][j] *= corr;
        }

        __syncthreads();  // all S-gemm reads of KPt done before P overwrite
        // Write P transposed into KPt: Pt[k][q]
        #pragma unroll
        for (int j = 0; j < 4; j++)
            *(float4*)&KPt[(tx*4 + j)*PAD + ty*4] =
                make_float4(s[0][j], s[1][j], s[2][j], s[3][j]);
        __syncthreads();

        // O += P @ V  (64x64x64)
        #pragma unroll
        for (int k = 0; k < 64; k++) {
            float4 a  = *(float4*)&KPt[k*PAD + ty*4];
            float4 bb = *(float4*)&Vs[k*PAD + tx*4];
            const float* ap = (const float*)&a;
            const float* bp = (const float*)&bb;
            #pragma unroll
            for (int i = 0; i < 4; i++)
                #pragma unroll
                for (int j = 0; j < 4; j++)
                    o[i][j] = fmaf(ap[i], bp[j], o[i][j]);
        }
    }

    float* Yb = Y + ((size_t)b * S_ + qt * 64) * H_;
    #pragma unroll
    for (int i = 0; i < 4; i++) {
        float inv = 1.0f / lrow[i];
        float4 r = make_float4(o[i][0]*inv, o[i][1]*inv, o[i][2]*inv, o[i][3]*inv);
        *(float4*)(Yb + (size_t)(ty*4 + i) * H_ + tx*4) = r;
    }
}

// ---------------------------------------------------------------------------
extern "C" void kernel_launch(void* const* d_in, const int* in_sizes, int n_in,
                              void* d_out, int out_size)
{
    const float* x  = (const float*)d_in[0];
    const float* wq = (const float*)d_in[1];
    const float* bq = (const float*)d_in[2];
    const float* wk = (const float*)d_in[3];
    const float* bk = (const float*)d_in[4];
    const float* wv = (const float*)d_in[5];
    const float* bv = (const float*)d_in[6];
    float* y = (float*)d_out;

    qkv_gemm_kernel<<<dim3(M_/64, 3), 256>>>(x, wq, bq, wk, bk, wv, bv);

    const int shmem = 3 * 64 * PAD * (int)sizeof(float);  // 52224 bytes
    cudaFuncSetAttribute(fa_kernel, cudaFuncAttributeMaxDynamicSharedMemorySize, shmem);
    fa_kernel<<<dim3(32, B_), 256, shmem>>>(y);
}

// round 7
// speedup vs baseline: 1.7391x; 1.7391x over previous
#include <cuda_runtime.h>
#include <cuda_bf16.h>
#include <cstdint>

#define B_ 8
#define S_ 2048
#define E_ 1024
#define H_ 64
#define M_ (B_*S_)

__device__ float g_q[M_*H_];
__device__ float g_k[M_*H_];
__device__ float g_v[M_*H_];

// ---------------------------------------------------------------------------
// mma.sync m16n8k16 bf16 helper (fp32 accumulate, D==C in place)
// ---------------------------------------------------------------------------
__device__ __forceinline__ void mma_bf16(float d[4], const uint32_t a[4], const uint32_t b[2]) {
    asm volatile(
        "mma.sync.aligned.m16n8k16.row.col.f32.bf16.bf16.f32 "
        "{%0,%1,%2,%3}, {%4,%5,%6,%7}, {%8,%9}, {%0,%1,%2,%3};\n"
        : "+f"(d[0]), "+f"(d[1]), "+f"(d[2]), "+f"(d[3])
        : "r"(a[0]), "r"(a[1]), "r"(a[2]), "r"(a[3]), "r"(b[0]), "r"(b[1]));
}

__device__ __forceinline__ void split_store(float v, __nv_bfloat16* ph, __nv_bfloat16* pl) {
    __nv_bfloat16 h = __float2bfloat16(v);
    *ph = h;
    *pl = __float2bfloat16(v - __bfloat162float(h));
}

// pack two floats -> bf16x2 (lo in low half)
__device__ __forceinline__ uint32_t pack2(float a, float b) {
    __nv_bfloat162 t = __floats2bfloat162_rn(a, b);
    return *reinterpret_cast<uint32_t*>(&t);
}

// ---------------------------------------------------------------------------
// Kernel 1: fused QKV projection via bf16 split MMA.
// Block: 128 threads (4 warps), 64 M-rows; N = 3 mats x 64 = 24 n8 tiles.
// K chunks of 32 (2 k16 steps). acc fp32 in registers.
// ---------------------------------------------------------------------------
#define XP 36   // smem k-pitch (bf16) for 32-wide chunks

__global__ __launch_bounds__(128) void qkv_mma(
    const float* __restrict__ x,
    const float* __restrict__ wq, const float* __restrict__ bq,
    const float* __restrict__ wk, const float* __restrict__ bk,
    const float* __restrict__ wv, const float* __restrict__ bv)
{
    __shared__ __nv_bfloat16 Xh[64][XP], Xl[64][XP];
    __shared__ __nv_bfloat16 Wh[192][XP], Wl[192][XP];   // Wt[mat*64+h][k], k contiguous

    const int t    = threadIdx.x;
    const int w    = t >> 5;
    const int lane = t & 31;
    const int m0   = blockIdx.x * 64;
    const int r0   = w * 16 + (lane >> 2);
    const int kq   = (lane & 3) * 2;

    const float* wm[3] = {wq, wk, wv};

    float acc[24][4];
    #pragma unroll
    for (int n = 0; n < 24; n++)
        #pragma unroll
        for (int i = 0; i < 4; i++) acc[n][i] = 0.f;

    for (int k0 = 0; k0 < E_; k0 += 32) {
        __syncthreads();
        // X chunk [64][32]
        #pragma unroll
        for (int i = 0; i < 4; i++) {
            int f = t + 128 * i;            // 0..511 float4s
            int r = f >> 3, c4 = (f & 7) * 4;
            float4 v = *(const float4*)(x + (size_t)(m0 + r) * E_ + k0 + c4);
            split_store(v.x, &Xh[r][c4+0], &Xl[r][c4+0]);
            split_store(v.y, &Xh[r][c4+1], &Xl[r][c4+1]);
            split_store(v.z, &Xh[r][c4+2], &Xl[r][c4+2]);
            split_store(v.w, &Xh[r][c4+3], &Xl[r][c4+3]);
        }
        // W chunks [32][64] x3, stored transposed
        #pragma unroll
        for (int i = 0; i < 12; i++) {
            int f   = t + 128 * i;          // 0..1535 float4s
            int mat = f >> 9, rem = f & 511;
            int kr  = rem >> 4, h4 = (rem & 15) * 4;
            float4 v = *(const float4*)(wm[mat] + (size_t)(k0 + kr) * H_ + h4);
            split_store(v.x, &Wh[mat*64 + h4+0][kr], &Wl[mat*64 + h4+0][kr]);
            split_store(v.y, &Wh[mat*64 + h4+1][kr], &Wl[mat*64 + h4+1][kr]);
            split_store(v.z, &Wh[mat*64 + h4+2][kr], &Wl[mat*64 + h4+2][kr]);
            split_store(v.w, &Wh[mat*64 + h4+3][kr], &Wl[mat*64 + h4+3][kr]);
        }
        __syncthreads();

        uint32_t Ah[2][4], Al[2][4];
        #pragma unroll
        for (int kk = 0; kk < 2; kk++) {
            int kb = kk * 16 + kq;
            Ah[kk][0] = *(const uint32_t*)&Xh[r0  ][kb  ];
            Ah[kk][1] = *(const uint32_t*)&Xh[r0+8][kb  ];
            Ah[kk][2] = *(const uint32_t*)&Xh[r0  ][kb+8];
            Ah[kk][3] = *(const uint32_t*)&Xh[r0+8][kb+8];
            Al[kk][0] = *(const uint32_t*)&Xl[r0  ][kb  ];
            Al[kk][1] = *(const uint32_t*)&Xl[r0+8][kb  ];
            Al[kk][2] = *(const uint32_t*)&Xl[r0  ][kb+8];
            Al[kk][3] = *(const uint32_t*)&Xl[r0+8][kb+8];
        }
        #pragma unroll
        for (int kk = 0; kk < 2; kk++) {
            int kb = kk * 16 + kq;
            #pragma unroll
            for (int g = 0; g < 3; g++) {          // groups of 8 n-tiles
                uint32_t Bh[8][2], Bl[8][2];
                #pragma unroll
                for (int j = 0; j < 8; j++) {
                    int br = (g*8 + j) * 8 + (lane >> 2);
                    Bh[j][0] = *(const uint32_t*)&Wh[br][kb  ];
                    Bh[j][1] = *(const uint32_t*)&Wh[br][kb+8];
                    Bl[j][0] = *(const uint32_t*)&Wl[br][kb  ];
                    Bl[j][1] = *(const uint32_t*)&Wl[br][kb+8];
                }
                #pragma unroll
                for (int j = 0; j < 8; j++) mma_bf16(acc[g*8+j], Ah[kk], Bh[j]);
                #pragma unroll
                for (int j = 0; j < 8; j++) mma_bf16(acc[g*8+j], Ah[kk], Bl[j]);
                #pragma unroll
                for (int j = 0; j < 8; j++) mma_bf16(acc[g*8+j], Al[kk], Bh[j]);
            }
        }
    }

    // epilogue: + bias, store fp32
    const float* bs[3] = {bq, bk, bv};
    float* outs[3];
    outs[0] = g_q; outs[1] = g_k; outs[2] = g_v;
    #pragma unroll
    for (int n = 0; n < 24; n++) {
        int mat = n / 8, j = n % 8;
        int col = j * 8 + kq;
        int row = m0 + r0;
        float b0 = bs[mat][col], b1 = bs[mat][col+1];
        float2 v0 = make_float2(acc[n][0] + b0, acc[n][1] + b1);
        float2 v1 = make_float2(acc[n][2] + b0, acc[n][3] + b1);
        *(float2*)(outs[mat] + (size_t)row * H_ + col)       = v0;
        *(float2*)(outs[mat] + (size_t)(row + 8) * H_ + col) = v1;
    }
}

// ---------------------------------------------------------------------------
// Kernel 2: causal flash attention via bf16 split MMA.
// Block: 128 threads (4 warps), 64 q rows; iterate 64-wide kv tiles.
// Q frags persistent in regs; P stays in regs between S-mma and PV-mma.
// ---------------------------------------------------------------------------
#define FP 72   // smem h/kv pitch (bf16) -> conflict-free frag loads

__global__ __launch_bounds__(128) void fa_mma(float* __restrict__ Y)
{
    extern __shared__ __align__(16) __nv_bfloat16 fsm[];
    __nv_bfloat16* Qh = fsm;
    __nv_bfloat16* Ql = fsm + 1*64*FP;
    __nv_bfloat16* Kh = fsm + 2*64*FP;
    __nv_bfloat16* Kl = fsm + 3*64*FP;
    __nv_bfloat16* Vh = fsm + 4*64*FP;
    __nv_bfloat16* Vl = fsm + 5*64*FP;

    const int b    = blockIdx.y;
    const int qt   = 31 - blockIdx.x;       // heavy tiles first
    const int t    = threadIdx.x;
    const int w    = t >> 5;
    const int lane = t & 31;
    const int rl   = lane >> 2;             // 0..7
    const int cq   = (lane & 3) * 2;        // 0,2,4,6
    const int qrow = w * 16 + rl;           // local q row (and +8)

    const float* __restrict__ Qb = g_q + ((size_t)b * S_ + qt * 64) * H_;
    const float* __restrict__ Kb = g_k + (size_t)b * S_ * H_;
    const float* __restrict__ Vb = g_v + (size_t)b * S_ * H_;

    // load Q tile (scaled by 1/8), split hi/lo
    #pragma unroll
    for (int i = 0; i < 8; i++) {
        int f = t + 128 * i;                // 0..1023 float4s
        int r = f >> 4, c4 = (f & 15) * 4;
        float4 v = *(const float4*)(Qb + (size_t)r * H_ + c4);
        split_store(v.x * 0.125f, &Qh[r*FP + c4+0], &Ql[r*FP + c4+0]);
        split_store(v.y * 0.125f, &Qh[r*FP + c4+1], &Ql[r*FP + c4+1]);
        split_store(v.z * 0.125f, &Qh[r*FP + c4+2], &Ql[r*FP + c4+2]);
        split_store(v.w * 0.125f, &Qh[r*FP + c4+3], &Ql[r*FP + c4+3]);
    }
    __syncthreads();

    // Q fragments, persistent
    uint32_t QAh[4][4], QAl[4][4];
    #pragma unroll
    for (int kk = 0; kk < 4; kk++) {
        int kb = kk * 16 + cq;
        QAh[kk][0] = *(const uint32_t*)&Qh[(qrow  )*FP + kb  ];
        QAh[kk][1] = *(const uint32_t*)&Qh[(qrow+8)*FP + kb  ];
        QAh[kk][2] = *(const uint32_t*)&Qh[(qrow  )*FP + kb+8];
        QAh[kk][3] = *(const uint32_t*)&Qh[(qrow+8)*FP + kb+8];
        QAl[kk][0] = *(const uint32_t*)&Ql[(qrow  )*FP + kb  ];
        QAl[kk][1] = *(const uint32_t*)&Ql[(qrow+8)*FP + kb  ];
        QAl[kk][2] = *(const uint32_t*)&Ql[(qrow  )*FP + kb+8];
        QAl[kk][3] = *(const uint32_t*)&Ql[(qrow+8)*FP + kb+8];
    }

    float o[8][4];
    #pragma unroll
    for (int j = 0; j < 8; j++)
        #pragma unroll
        for (int i = 0; i < 4; i++) o[j][i] = 0.f;
    float mrow[2] = {-1e30f, -1e30f};
    float lrow[2] = {0.f, 0.f};

    for (int kt = 0; kt <= qt; kt++) {
        __syncthreads();   // prior iter's smem reads done
        #pragma unroll
        for (int i = 0; i < 8; i++) {
            int f = t + 128 * i;
            int r = f >> 4, c4 = (f & 15) * 4;
            const float* kp = Kb + (size_t)(kt * 64 + r) * H_ + c4;
            float4 kv = *(const float4*)kp;
            split_store(kv.x, &Kh[r*FP + c4+0], &Kl[r*FP + c4+0]);
            split_store(kv.y, &Kh[r*FP + c4+1], &Kl[r*FP + c4+1]);
            split_store(kv.z, &Kh[r*FP + c4+2], &Kl[r*FP + c4+2]);
            split_store(kv.w, &Kh[r*FP + c4+3], &Kl[r*FP + c4+3]);
            float4 vv = *(const float4*)(Vb + (size_t)(kt * 64 + r) * H_ + c4);
            split_store(vv.x, &Vh[r*FP + c4+0], &Vl[r*FP + c4+0]);
            split_store(vv.y, &Vh[r*FP + c4+1], &Vl[r*FP + c4+1]);
            split_store(vv.z, &Vh[r*FP + c4+2], &Vl[r*FP + c4+2]);
            split_store(vv.w, &Vh[r*FP + c4+3], &Vl[r*FP + c4+3]);
        }
        __syncthreads();

        // ---- S = Qs @ K^T ----
        float s[8][4];
        #pragma unroll
        for (int j = 0; j < 8; j++)
            #pragma unroll
            for (int i = 0; i < 4; i++) s[j][i] = 0.f;

        #pragma unroll
        for (int kk = 0; kk < 4; kk++) {
            int kb = kk * 16 + cq;
            uint32_t Bh[8][2], Bl[8][2];
            #pragma unroll
            for (int j = 0; j < 8; j++) {
                int br = (j * 8 + rl) * FP;
                Bh[j][0] = *(const uint32_t*)&Kh[br + kb  ];
                Bh[j][1] = *(const uint32_t*)&Kh[br + kb+8];
                Bl[j][0] = *(const uint32_t*)&Kl[br + kb  ];
                Bl[j][1] = *(const uint32_t*)&Kl[br + kb+8];
            }
            #pragma unroll
            for (int j = 0; j < 8; j++) mma_bf16(s[j], QAh[kk], Bh[j]);
            #pragma unroll
            for (int j = 0; j < 8; j++) mma_bf16(s[j], QAh[kk], Bl[j]);
            #pragma unroll
            for (int j = 0; j < 8; j++) mma_bf16(s[j], QAl[kk], Bh[j]);
        }

        // causal mask on the diagonal tile (local row/col compare valid: same tile base)
        if (kt == qt) {
            #pragma unroll
            for (int j = 0; j < 8; j++) {
                int c0 = j * 8 + cq;
                if (c0     > qrow)     s[j][0] = -1e30f;
                if (c0 + 1 > qrow)     s[j][1] = -1e30f;
                if (c0     > qrow + 8) s[j][2] = -1e30f;
                if (c0 + 1 > qrow + 8) s[j][3] = -1e30f;
            }
        }

        // ---- online softmax (rows qrow, qrow+8; quad-reduced) ----
        float mx0 = -1e30f, mx1 = -1e30f;
        #pragma unroll
        for (int j = 0; j < 8; j++) {
            mx0 = fmaxf(mx0, fmaxf(s[j][0], s[j][1]));
            mx1 = fmaxf(mx1, fmaxf(s[j][2], s[j][3]));
        }
        mx0 = fmaxf(mx0, __shfl_xor_sync(0xffffffffu, mx0, 1));
        mx0 = fmaxf(mx0, __shfl_xor_sync(0xffffffffu, mx0, 2));
        mx1 = fmaxf(mx1, __shfl_xor_sync(0xffffffffu, mx1, 1));
        mx1 = fmaxf(mx1, __shfl_xor_sync(0xffffffffu, mx1, 2));

        float mn0 = fmaxf(mrow[0], mx0), mn1 = fmaxf(mrow[1], mx1);
        float corr0 = __expf(mrow[0] - mn0), corr1 = __expf(mrow[1] - mn1);
        mrow[0] = mn0; mrow[1] = mn1;

        float sum0 = 0.f, sum1 = 0.f;
        #pragma unroll
        for (int j = 0; j < 8; j++) {
            s[j][0] = __expf(s[j][0] - mn0);
            s[j][1] = __expf(s[j][1] - mn0);
            s[j][2] = __expf(s[j][2] - mn1);
            s[j][3] = __expf(s[j][3] - mn1);
            sum0 += s[j][0] + s[j][1];
            sum1 += s[j][2] + s[j][3];
        }
        sum0 += __shfl_xor_sync(0xffffffffu, sum0, 1);
        sum0 += __shfl_xor_sync(0xffffffffu, sum0, 2);
        sum1 += __shfl_xor_sync(0xffffffffu, sum1, 1);
        sum1 += __shfl_xor_sync(0xffffffffu, sum1, 2);
        lrow[0] = lrow[0] * corr0 + sum0;
        lrow[1] = lrow[1] * corr1 + sum1;

        #pragma unroll
        for (int j = 0; j < 8; j++) {
            o[j][0] *= corr0; o[j][1] *= corr0;
            o[j][2] *= corr1; o[j][3] *= corr1;
        }

        // ---- P fragments (hi/lo) from s registers ----
        uint32_t Ph[4][4], Pl[4][4];
        #pragma unroll
        for (int kk = 0; kk < 4; kk++) {
            int j0 = 2*kk, j1 = 2*kk + 1;
            #pragma unroll
            for (int half = 0; half < 2; half++) {
                int jj = half ? j1 : j0;
                // a0/a2: row qrow (c0,c1);  a1/a3: row qrow+8 (c2,c3)
                __nv_bfloat162 h0 = __floats2bfloat162_rn(s[jj][0], s[jj][1]);
                __nv_bfloat162 h1 = __floats2bfloat162_rn(s[jj][2], s[jj][3]);
                Ph[kk][half*2 + 0] = *reinterpret_cast<uint32_t*>(&h0);
                Ph[kk][half*2 + 1] = *reinterpret_cast<uint32_t*>(&h1);
                Pl[kk][half*2 + 0] = pack2(s[jj][0] - __low2float(h0), s[jj][1] - __high2float(h0));
                Pl[kk][half*2 + 1] = pack2(s[jj][2] - __low2float(h1), s[jj][3] - __high2float(h1));
            }
        }

        // ---- O += P @ V ----
        #pragma unroll
        for (int kk = 0; kk < 4; kk++) {
            int kv0 = kk * 16 + cq;
            uint32_t Bh[8][2], Bl[8][2];
            #pragma unroll
            for (int jh = 0; jh < 8; jh++) {
                int h = jh * 8 + rl;
                Bh[jh][0] = (uint32_t)*(const uint16_t*)&Vh[(kv0  )*FP + h]
                          | ((uint32_t)*(const uint16_t*)&Vh[(kv0+1)*FP + h] << 16);
                Bh[jh][1] = (uint32_t)*(const uint16_t*)&Vh[(kv0+8)*FP + h]
                          | ((uint32_t)*(const uint16_t*)&Vh[(kv0+9)*FP + h] << 16);
                Bl[jh][0] = (uint32_t)*(const uint16_t*)&Vl[(kv0  )*FP + h]
                          | ((uint32_t)*(const uint16_t*)&Vl[(kv0+1)*FP + h] << 16);
                Bl[jh][1] = (uint32_t)*(const uint16_t*)&Vl[(kv0+8)*FP + h]
                          | ((uint32_t)*(const uint16_t*)&Vl[(kv0+9)*FP + h] << 16);
            }
            #pragma unroll
            for (int jh = 0; jh < 8; jh++) mma_bf16(o[jh], Ph[kk], Bh[jh]);
            #pragma unroll
            for (int jh = 0; jh < 8; jh++) mma_bf16(o[jh], Ph[kk], Bl[jh]);
            #pragma unroll
            for (int jh = 0; jh < 8; jh++) mma_bf16(o[jh], Pl[kk], Bh[jh]);
        }
    }

    // epilogue
    float inv0 = 1.0f / lrow[0], inv1 = 1.0f / lrow[1];
    float* Yb = Y + ((size_t)b * S_ + qt * 64) * H_;
    #pragma unroll
    for (int jh = 0; jh < 8; jh++) {
        int col = jh * 8 + cq;
        float2 v0 = make_float2(o[jh][0] * inv0, o[jh][1] * inv0);
        float2 v1 = make_float2(o[jh][2] * inv1, o[jh][3] * inv1);
        *(float2*)(Yb + (size_t)(qrow    ) * H_ + col) = v0;
        *(float2*)(Yb + (size_t)(qrow + 8) * H_ + col) = v1;
    }
}

// ---------------------------------------------------------------------------
extern "C" void kernel_launch(void* const* d_in, const int* in_sizes, int n_in,
                              void* d_out, int out_size)
{
    const float* x  = (const float*)d_in[0];
    const float* wq = (const float*)d_in[1];
    const float* bq = (const float*)d_in[2];
    const float* wk = (const float*)d_in[3];
    const float* bk = (const float*)d_in[4];
    const float* wv = (const float*)d_in[5];
    const float* bv = (const float*)d_in[6];
    float* y = (float*)d_out;

    qkv_mma<<<M_/64, 128>>>(x, wq, bq, wk, bk, wv, bv);

    const int shmem = 6 * 64 * FP * (int)sizeof(__nv_bfloat16);   // 55296 B
    cudaFuncSetAttribute(fa_mma, cudaFuncAttributeMaxDynamicSharedMemorySize, shmem);
    fa_mma<<<dim3(32, B_), 128, shmem>>>(y);
}

// round 8
// speedup vs baseline: 2.9711x; 1.7084x over previous
#include <cuda_runtime.h>
#include <cuda_bf16.h>
#include <cstdint>

#define B_ 8
#define S_ 2048
#define E_ 1024
#define H_ 64
#define M_ (B_*S_)
#define WP 72   // smem pitch (bf16)

// bf16 hi/lo projected tensors (q pre-scaled by 1/8)
__device__ __nv_bfloat16 g_qh[M_*H_], g_ql[M_*H_];
__device__ __nv_bfloat16 g_kh[M_*H_], g_kl[M_*H_];
__device__ __nv_bfloat16 g_vh[M_*H_], g_vl[M_*H_];
// pre-split, transposed weights: [3*64][1024] (k contiguous)
__device__ __nv_bfloat16 g_wh[192*E_], g_wl[192*E_];

__device__ __forceinline__ void mma_bf16(float d[4], const uint32_t a[4], const uint32_t b[2]) {
    asm volatile(
        "mma.sync.aligned.m16n8k16.row.col.f32.bf16.bf16.f32 "
        "{%0,%1,%2,%3}, {%4,%5,%6,%7}, {%8,%9}, {%0,%1,%2,%3};\n"
        : "+f"(d[0]), "+f"(d[1]), "+f"(d[2]), "+f"(d[3])
        : "r"(a[0]), "r"(a[1]), "r"(a[2]), "r"(a[3]), "r"(b[0]), "r"(b[1]));
}

__device__ __forceinline__ void split2(float a, float b, uint32_t& h, uint32_t& l) {
    __nv_bfloat162 hb = __floats2bfloat162_rn(a, b);
    h = *reinterpret_cast<uint32_t*>(&hb);
    __nv_bfloat162 lb = __floats2bfloat162_rn(a - __low2float(hb), b - __high2float(hb));
    l = *reinterpret_cast<uint32_t*>(&lb);
}

// ---------------------------------------------------------------------------
// convert_w: W [1024][64] fp32 x3 -> g_wh/g_wl [192][1024] bf16 (transposed)
// ---------------------------------------------------------------------------
__global__ void convert_w(const float* __restrict__ wq, const float* __restrict__ wk,
                          const float* __restrict__ wv)
{
    const int row = blockIdx.x;           // 0..191: mat*64 + h
    const int mat = row >> 6, h = row & 63;
    const float* w = (mat==0) ? wq : ((mat==1) ? wk : wv);
    for (int k = threadIdx.x; k < E_; k += blockDim.x) {
        float v = w[(size_t)k * H_ + h];
        __nv_bfloat16 hi = __float2bfloat16(v);
        g_wh[(size_t)row * E_ + k] = hi;
        g_wl[(size_t)row * E_ + k] = __float2bfloat16(v - __bfloat162float(hi));
    }
}

// ---------------------------------------------------------------------------
// qkv: 256 threads, 64-row M tile, N=192 (warp: 16 rows x 96 cols), BK=64
// ---------------------------------------------------------------------------
__global__ __launch_bounds__(256) void qkv_mma(
    const float* __restrict__ x,
    const float* __restrict__ bq, const float* __restrict__ bk, const float* __restrict__ bv)
{
    extern __shared__ __align__(16) __nv_bfloat16 qsm[];
    __nv_bfloat16* Xh = qsm;              // [64][WP]
    __nv_bfloat16* Xl = qsm + 4608;
    __nv_bfloat16* Wh = qsm + 9216;       // [192][WP]
    __nv_bfloat16* Wl = qsm + 23040;

    const int t    = threadIdx.x;
    const int w    = t >> 5;
    const int lane = t & 31;
    const int rl   = lane >> 2;
    const int kq   = (lane & 3) * 2;
    const int msub = w & 3;
    const int nhalf= w >> 2;
    const int m0   = blockIdx.x * 64;
    const int r0   = msub * 16 + rl;

    float acc[12][4];
    #pragma unroll
    for (int j = 0; j < 12; j++)
        #pragma unroll
        for (int i = 0; i < 4; i++) acc[j][i] = 0.f;

    for (int k0 = 0; k0 < E_; k0 += 64) {
        __syncthreads();
        // X chunk [64][64] fp32 -> split hi/lo
        #pragma unroll
        for (int i = 0; i < 2; i++) {
            int f = t + 256 * i;               // 0..511
            int r = f >> 3, c8 = (f & 7) * 8;
            const float* xp = x + (size_t)(m0 + r) * E_ + k0 + c8;
            float4 a = *(const float4*)xp;
            float4 b = *(const float4*)(xp + 4);
            uint4 hi, lo;
            split2(a.x, a.y, hi.x, lo.x);
            split2(a.z, a.w, hi.y, lo.y);
            split2(b.x, b.y, hi.z, lo.z);
            split2(b.z, b.w, hi.w, lo.w);
            *(uint4*)&Xh[r*WP + c8] = hi;
            *(uint4*)&Xl[r*WP + c8] = lo;
        }
        // W chunk [192][64] bf16 copies
        #pragma unroll
        for (int i = 0; i < 6; i++) {
            int f = t + 256 * i;               // 0..1535
            int r = f >> 3, c8 = (f & 7) * 8;
            *(uint4*)&Wh[r*WP + c8] = *(const uint4*)&g_wh[(size_t)r * E_ + k0 + c8];
            *(uint4*)&Wl[r*WP + c8] = *(const uint4*)&g_wl[(size_t)r * E_ + k0 + c8];
        }
        __syncthreads();

        #pragma unroll
        for (int kk = 0; kk < 4; kk++) {
            int kb = kk * 16 + kq;
            uint32_t Ah[4], Al[4];
            Ah[0] = *(const uint32_t*)&Xh[(r0  )*WP + kb  ];
            Ah[1] = *(const uint32_t*)&Xh[(r0+8)*WP + kb  ];
            Ah[2] = *(const uint32_t*)&Xh[(r0  )*WP + kb+8];
            Ah[3] = *(const uint32_t*)&Xh[(r0+8)*WP + kb+8];
            Al[0] = *(const uint32_t*)&Xl[(r0  )*WP + kb  ];
            Al[1] = *(const uint32_t*)&Xl[(r0+8)*WP + kb  ];
            Al[2] = *(const uint32_t*)&Xl[(r0  )*WP + kb+8];
            Al[3] = *(const uint32_t*)&Xl[(r0+8)*WP + kb+8];
            uint32_t Bh[12][2], Bl[12][2];
            #pragma unroll
            for (int j = 0; j < 12; j++) {
                int br = ((nhalf*12 + j) * 8 + rl) * WP;
                Bh[j][0] = *(const uint32_t*)&Wh[br + kb  ];
                Bh[j][1] = *(const uint32_t*)&Wh[br + kb+8];
                Bl[j][0] = *(const uint32_t*)&Wl[br + kb  ];
                Bl[j][1] = *(const uint32_t*)&Wl[br + kb+8];
            }
            #pragma unroll
            for (int j = 0; j < 12; j++) mma_bf16(acc[j], Ah, Bh[j]);
            #pragma unroll
            for (int j = 0; j < 12; j++) mma_bf16(acc[j], Ah, Bl[j]);
            #pragma unroll
            for (int j = 0; j < 12; j++) mma_bf16(acc[j], Al, Bh[j]);
        }
    }

    // epilogue: +bias, scale q by 1/8, split hi/lo, store bf16
    const float* bs[3] = {bq, bk, bv};
    __nv_bfloat16* oh[3] = {g_qh, g_kh, g_vh};
    __nv_bfloat16* ol[3] = {g_ql, g_kl, g_vl};
    #pragma unroll
    for (int j = 0; j < 12; j++) {
        int gn = nhalf*12 + j;
        int ct = gn * 8 + kq;
        int mat = ct >> 6, cl = ct & 63;
        float sc = (mat == 0) ? 0.125f : 1.0f;
        float b0 = bs[mat][cl], b1 = bs[mat][cl+1];
        size_t row = (size_t)(m0 + r0);
        uint32_t h0, l0, h1, l1;
        split2((acc[j][0] + b0) * sc, (acc[j][1] + b1) * sc, h0, l0);
        split2((acc[j][2] + b0) * sc, (acc[j][3] + b1) * sc, h1, l1);
        *(uint32_t*)&oh[mat][ row      * H_ + cl] = h0;
        *(uint32_t*)&ol[mat][ row      * H_ + cl] = l0;
        *(uint32_t*)&oh[mat][(row + 8) * H_ + cl] = h1;
        *(uint32_t*)&ol[mat][(row + 8) * H_ + cl] = l1;
    }
}

// ---------------------------------------------------------------------------
// fa: 256 threads = 2 warp-groups; group g handles kt = g, g+2, ...
// private K/V smem per group (named barriers); merge softmax states at end.
// ---------------------------------------------------------------------------
__global__ __launch_bounds__(256) void fa_mma(float* __restrict__ Y)
{
    extern __shared__ __align__(16) __nv_bfloat16 fsm[];
    __nv_bfloat16* Qh = fsm;                       // [64][WP]
    __nv_bfloat16* Ql = fsm + 4608;

    const int b    = blockIdx.y;
    const int qt   = 31 - blockIdx.x;              // heavy tiles first
    const int t    = threadIdx.x;
    const int w    = t >> 5;
    const int lane = t & 31;
    const int rl   = lane >> 2;
    const int cq   = (lane & 3) * 2;
    const int g    = w >> 2;                       // warp group 0/1
    const int qrow = (w & 3) * 16 + rl;
    const int gt   = t & 127;

    __nv_bfloat16* Kh = fsm + 9216 + g * 18432;
    __nv_bfloat16* Kl = Kh + 4608;
    __nv_bfloat16* Vh = Kh + 9216;
    __nv_bfloat16* Vl = Kh + 13824;

    const size_t qbase  = (size_t)(b * S_ + qt * 64);
    const size_t kvbase = (size_t)b * S_;

    // Q tile (already scaled, pre-split)
    #pragma unroll
    for (int i = 0; i < 2; i++) {
        int f = t + 256 * i;                 // 0..511
        int r = f >> 3, c8 = (f & 7) * 8;
        *(uint4*)&Qh[r*WP + c8] = *(const uint4*)&g_qh[(qbase + r) * H_ + c8];
        *(uint4*)&Ql[r*WP + c8] = *(const uint4*)&g_ql[(qbase + r) * H_ + c8];
    }
    __syncthreads();

    uint32_t QAh[4][4], QAl[4][4];
    #pragma unroll
    for (int kk = 0; kk < 4; kk++) {
        int kb = kk * 16 + cq;
        QAh[kk][0] = *(const uint32_t*)&Qh[(qrow  )*WP + kb  ];
        QAh[kk][1] = *(const uint32_t*)&Qh[(qrow+8)*WP + kb  ];
        QAh[kk][2] = *(const uint32_t*)&Qh[(qrow  )*WP + kb+8];
        QAh[kk][3] = *(const uint32_t*)&Qh[(qrow+8)*WP + kb+8];
        QAl[kk][0] = *(const uint32_t*)&Ql[(qrow  )*WP + kb  ];
        QAl[kk][1] = *(const uint32_t*)&Ql[(qrow+8)*WP + kb  ];
        QAl[kk][2] = *(const uint32_t*)&Ql[(qrow  )*WP + kb+8];
        QAl[kk][3] = *(const uint32_t*)&Ql[(qrow+8)*WP + kb+8];
    }

    float o[8][4];
    #pragma unroll
    for (int j = 0; j < 8; j++)
        #pragma unroll
        for (int i = 0; i < 4; i++) o[j][i] = 0.f;
    float mrow[2] = {-1e30f, -1e30f};
    float lrow[2] = {0.f, 0.f};

    for (int kt = g; kt <= qt; kt += 2) {
        asm volatile("bar.sync %0, 128;" :: "r"(1 + g) : "memory");
        #pragma unroll
        for (int i = 0; i < 4; i++) {
            int f = gt + 128 * i;            // 0..511
            int r = f >> 3, c8 = (f & 7) * 8;
            size_t gi = (kvbase + kt * 64 + r) * H_ + c8;
            *(uint4*)&Kh[r*WP + c8] = *(const uint4*)&g_kh[gi];
            *(uint4*)&Kl[r*WP + c8] = *(const uint4*)&g_kl[gi];
            *(uint4*)&Vh[r*WP + c8] = *(const uint4*)&g_vh[gi];
            *(uint4*)&Vl[r*WP + c8] = *(const uint4*)&g_vl[gi];
        }
        asm volatile("bar.sync %0, 128;" :: "r"(1 + g) : "memory");

        // ---- S = Qs @ K^T ----
        float s[8][4];
        #pragma unroll
        for (int j = 0; j < 8; j++)
            #pragma unroll
            for (int i = 0; i < 4; i++) s[j][i] = 0.f;

        #pragma unroll
        for (int kk = 0; kk < 4; kk++) {
            int kb = kk * 16 + cq;
            uint32_t Bh[8][2], Bl[8][2];
            #pragma unroll
            for (int j = 0; j < 8; j++) {
                int br = (j * 8 + rl) * WP;
                Bh[j][0] = *(const uint32_t*)&Kh[br + kb  ];
                Bh[j][1] = *(const uint32_t*)&Kh[br + kb+8];
                Bl[j][0] = *(const uint32_t*)&Kl[br + kb  ];
                Bl[j][1] = *(const uint32_t*)&Kl[br + kb+8];
            }
            #pragma unroll
            for (int j = 0; j < 8; j++) mma_bf16(s[j], QAh[kk], Bh[j]);
            #pragma unroll
            for (int j = 0; j < 8; j++) mma_bf16(s[j], QAh[kk], Bl[j]);
            #pragma unroll
            for (int j = 0; j < 8; j++) mma_bf16(s[j], QAl[kk], Bh[j]);
        }

        if (kt == qt) {
            #pragma unroll
            for (int j = 0; j < 8; j++) {
                int c0 = j * 8 + cq;
                if (c0     > qrow)     s[j][0] = -1e30f;
                if (c0 + 1 > qrow)     s[j][1] = -1e30f;
                if (c0     > qrow + 8) s[j][2] = -1e30f;
                if (c0 + 1 > qrow + 8) s[j][3] = -1e30f;
            }
        }

        // ---- online softmax ----
        float mx0 = -1e30f, mx1 = -1e30f;
        #pragma unroll
        for (int j = 0; j < 8; j++) {
            mx0 = fmaxf(mx0, fmaxf(s[j][0], s[j][1]));
            mx1 = fmaxf(mx1, fmaxf(s[j][2], s[j][3]));
        }
        mx0 = fmaxf(mx0, __shfl_xor_sync(0xffffffffu, mx0, 1));
        mx0 = fmaxf(mx0, __shfl_xor_sync(0xffffffffu, mx0, 2));
        mx1 = fmaxf(mx1, __shfl_xor_sync(0xffffffffu, mx1, 1));
        mx1 = fmaxf(mx1, __shfl_xor_sync(0xffffffffu, mx1, 2));

        float mn0 = fmaxf(mrow[0], mx0), mn1 = fmaxf(mrow[1], mx1);
        float corr0 = __expf(mrow[0] - mn0), corr1 = __expf(mrow[1] - mn1);
        mrow[0] = mn0; mrow[1] = mn1;

        float sum0 = 0.f, sum1 = 0.f;
        #pragma unroll
        for (int j = 0; j < 8; j++) {
            s[j][0] = __expf(s[j][0] - mn0);
            s[j][1] = __expf(s[j][1] - mn0);
            s[j][2] = __expf(s[j][2] - mn1);
            s[j][3] = __expf(s[j][3] - mn1);
            sum0 += s[j][0] + s[j][1];
            sum1 += s[j][2] + s[j][3];
        }
        sum0 += __shfl_xor_sync(0xffffffffu, sum0, 1);
        sum0 += __shfl_xor_sync(0xffffffffu, sum0, 2);
        sum1 += __shfl_xor_sync(0xffffffffu, sum1, 1);
        sum1 += __shfl_xor_sync(0xffffffffu, sum1, 2);
        lrow[0] = lrow[0] * corr0 + sum0;
        lrow[1] = lrow[1] * corr1 + sum1;

        #pragma unroll
        for (int j = 0; j < 8; j++) {
            o[j][0] *= corr0; o[j][1] *= corr0;
            o[j][2] *= corr1; o[j][3] *= corr1;
        }

        // ---- P frags (hi/lo) in regs ----
        uint32_t Ph[4][4], Pl[4][4];
        #pragma unroll
        for (int kk = 0; kk < 4; kk++) {
            #pragma unroll
            for (int half = 0; half < 2; half++) {
                int jj = 2*kk + half;
                split2(s[jj][0], s[jj][1], Ph[kk][half*2+0], Pl[kk][half*2+0]);
                split2(s[jj][2], s[jj][3], Ph[kk][half*2+1], Pl[kk][half*2+1]);
            }
        }

        // ---- O += P @ V ----
        #pragma unroll
        for (int kk = 0; kk < 4; kk++) {
            int kv0 = kk * 16 + cq;
            uint32_t Bh[8][2], Bl[8][2];
            #pragma unroll
            for (int jh = 0; jh < 8; jh++) {
                int h = jh * 8 + rl;
                Bh[jh][0] = (uint32_t)*(const uint16_t*)&Vh[(kv0  )*WP + h]
                          | ((uint32_t)*(const uint16_t*)&Vh[(kv0+1)*WP + h] << 16);
                Bh[jh][1] = (uint32_t)*(const uint16_t*)&Vh[(kv0+8)*WP + h]
                          | ((uint32_t)*(const uint16_t*)&Vh[(kv0+9)*WP + h] << 16);
                Bl[jh][0] = (uint32_t)*(const uint16_t*)&Vl[(kv0  )*WP + h]
                          | ((uint32_t)*(const uint16_t*)&Vl[(kv0+1)*WP + h] << 16);
                Bl[jh][1] = (uint32_t)*(const uint16_t*)&Vl[(kv0+8)*WP + h]
                          | ((uint32_t)*(const uint16_t*)&Vl[(kv0+9)*WP + h] << 16);
            }
            #pragma unroll
            for (int jh = 0; jh < 8; jh++) mma_bf16(o[jh], Ph[kk], Bh[jh]);
            #pragma unroll
            for (int jh = 0; jh < 8; jh++) mma_bf16(o[jh], Ph[kk], Bl[jh]);
            #pragma unroll
            for (int jh = 0; jh < 8; jh++) mma_bf16(o[jh], Pl[kk], Bh[jh]);
        }
    }

    // ---- merge the two groups' partial states ----
    float* mbuf = (float*)((char*)fsm + 55296);   // inside group-1 KV region; stride 37
    if (g == 1) {
        float* p = mbuf + gt * 37;
        p[0] = mrow[0]; p[1] = mrow[1]; p[2] = lrow[0]; p[3] = lrow[1];
        #pragma unroll
        for (int j = 0; j < 8; j++)
            #pragma unroll
            for (int i = 0; i < 4; i++) p[4 + j*4 + i] = o[j][i];
    }
    __syncthreads();
    if (g == 0) {
        const float* p = mbuf + gt * 37;
        float m1a = p[0], m1b = p[1], l1a = p[2], l1b = p[3];
        float mA = fmaxf(mrow[0], m1a), mB = fmaxf(mrow[1], m1b);
        float w0a = __expf(mrow[0] - mA), w1a = __expf(m1a - mA);
        float w0b = __expf(mrow[1] - mB), w1b = __expf(m1b - mB);
        float invA = 1.0f / (lrow[0] * w0a + l1a * w1a);
        float invB = 1.0f / (lrow[1] * w0b + l1b * w1b);
        float* Yb = Y + qbase * H_;
        #pragma unroll
        for (int j = 0; j < 8; j++) {
            int col = j * 8 + cq;
            float oa0 = (o[j][0] * w0a + p[4 + j*4 + 0] * w1a) * invA;
            float oa1 = (o[j][1] * w0a + p[4 + j*4 + 1] * w1a) * invA;
            float ob0 = (o[j][2] * w0b + p[4 + j*4 + 2] * w1b) * invB;
            float ob1 = (o[j][3] * w0b + p[4 + j*4 + 3] * w1b) * invB;
            *(float2*)(Yb + (size_t)(qrow    ) * H_ + col) = make_float2(oa0, oa1);
            *(float2*)(Yb + (size_t)(qrow + 8) * H_ + col) = make_float2(ob0, ob1);
        }
    }
}

// ---------------------------------------------------------------------------
extern "C" void kernel_launch(void* const* d_in, const int* in_sizes, int n_in,
                              void* d_out, int out_size)
{
    const float* x  = (const float*)d_in[0];
    const float* wq = (const float*)d_in[1];
    const float* bq = (const float*)d_in[2];
    const float* wk = (const float*)d_in[3];
    const float* bk = (const float*)d_in[4];
    const float* wv = (const float*)d_in[5];
    const float* bv = (const float*)d_in[6];
    float* y = (float*)d_out;

    convert_w<<<192, 256>>>(wq, wk, wv);

    const int qsh = (4608*2 + 13824*2) * (int)sizeof(__nv_bfloat16);  // 73728
    cudaFuncSetAttribute(qkv_mma, cudaFuncAttributeMaxDynamicSharedMemorySize, qsh);
    qkv_mma<<<M_/64, 256, qsh>>>(x, bq, bk, bv);

    const int fsh = (9216 + 2*18432) * (int)sizeof(__nv_bfloat16);    // 92160
    cudaFuncSetAttribute(fa_mma, cudaFuncAttributeMaxDynamicSharedMemorySize, fsh);
    fa_mma<<<dim3(32, B_), 256, fsh>>>(y);
}

// round 9
// speedup vs baseline: 3.2931x; 1.1084x over previous
#include <cuda_runtime.h>
#include <cuda_bf16.h>
#include <cstdint>

#define B_ 8
#define S_ 2048
#define E_ 1024
#define H_ 64
#define M_ (B_*S_)
#define WP 72   // smem pitch (bf16)

// bf16 hi/lo projected tensors (q pre-scaled by 1/8)
__device__ __nv_bfloat16 g_qh[M_*H_], g_ql[M_*H_];
__device__ __nv_bfloat16 g_kh[M_*H_], g_kl[M_*H_];
__device__ __nv_bfloat16 g_vh[M_*H_], g_vl[M_*H_];
// pre-split, transposed weights: [3*64][1024] (k contiguous)
__device__ __nv_bfloat16 g_wh[192*E_], g_wl[192*E_];

__device__ __forceinline__ void mma_bf16(float d[4], const uint32_t a[4], const uint32_t b[2]) {
    asm volatile(
        "mma.sync.aligned.m16n8k16.row.col.f32.bf16.bf16.f32 "
        "{%0,%1,%2,%3}, {%4,%5,%6,%7}, {%8,%9}, {%0,%1,%2,%3};\n"
        : "+f"(d[0]), "+f"(d[1]), "+f"(d[2]), "+f"(d[3])
        : "r"(a[0]), "r"(a[1]), "r"(a[2]), "r"(a[3]), "r"(b[0]), "r"(b[1]));
}

__device__ __forceinline__ void ldsm4(uint32_t& d0, uint32_t& d1, uint32_t& d2, uint32_t& d3,
                                      const void* p) {
    uint32_t a = (uint32_t)__cvta_generic_to_shared(p);
    asm volatile("ldmatrix.sync.aligned.m8n8.x4.shared.b16 {%0,%1,%2,%3}, [%4];"
        : "=r"(d0), "=r"(d1), "=r"(d2), "=r"(d3) : "r"(a));
}
__device__ __forceinline__ void ldsm4t(uint32_t& d0, uint32_t& d1, uint32_t& d2, uint32_t& d3,
                                       const void* p) {
    uint32_t a = (uint32_t)__cvta_generic_to_shared(p);
    asm volatile("ldmatrix.sync.aligned.m8n8.x4.trans.shared.b16 {%0,%1,%2,%3}, [%4];"
        : "=r"(d0), "=r"(d1), "=r"(d2), "=r"(d3) : "r"(a));
}

__device__ __forceinline__ void split2(float a, float b, uint32_t& h, uint32_t& l) {
    __nv_bfloat162 hb = __floats2bfloat162_rn(a, b);
    h = *reinterpret_cast<uint32_t*>(&hb);
    __nv_bfloat162 lb = __floats2bfloat162_rn(a - __low2float(hb), b - __high2float(hb));
    l = *reinterpret_cast<uint32_t*>(&lb);
}

// ---------------------------------------------------------------------------
// convert_w: coalesced smem transpose. grid (16, 3), 256 threads.
// ---------------------------------------------------------------------------
__global__ __launch_bounds__(256) void convert_w(
    const float* __restrict__ wq, const float* __restrict__ wk, const float* __restrict__ wv)
{
    __shared__ float T[64][65];
    const int mat = blockIdx.y;
    const float* w = (mat==0) ? wq : ((mat==1) ? wk : wv);
    const int k0 = blockIdx.x * 64;
    const int t = threadIdx.x;
    #pragma unroll
    for (int i = 0; i < 16; i++) {
        int f = t + 256 * i;           // 0..4095
        int k = f >> 6, h = f & 63;
        T[k][h] = w[(size_t)(k0 + k) * H_ + h];
    }
    __syncthreads();
    #pragma unroll
    for (int i = 0; i < 16; i++) {
        int f = t + 256 * i;
        int h = f >> 6, k = f & 63;    // lanes: consecutive k -> coalesced global writes
        float v = T[k][h];
        __nv_bfloat16 hi = __float2bfloat16(v);
        g_wh[(size_t)(mat*64 + h) * E_ + k0 + k] = hi;
        g_wl[(size_t)(mat*64 + h) * E_ + k0 + k] = __float2bfloat16(v - __bfloat162float(hi));
    }
}

// ---------------------------------------------------------------------------
// qkv: 256 threads, 64-row M tile, N=192 (warp: 16 rows x 96 cols), BK=64
// ---------------------------------------------------------------------------
__global__ __launch_bounds__(256) void qkv_mma(
    const float* __restrict__ x,
    const float* __restrict__ bq, const float* __restrict__ bk, const float* __restrict__ bv)
{
    extern __shared__ __align__(16) __nv_bfloat16 qsm[];
    __nv_bfloat16* Xh = qsm;              // [64][WP]
    __nv_bfloat16* Xl = qsm + 4608;
    __nv_bfloat16* Wh = qsm + 9216;       // [192][WP]
    __nv_bfloat16* Wl = qsm + 23040;

    const int t    = threadIdx.x;
    const int w    = t >> 5;
    const int lane = t & 31;
    const int rl   = lane >> 2;
    const int kq   = (lane & 3) * 2;
    const int msub = w & 3;
    const int nhalf= w >> 2;
    const int m0   = blockIdx.x * 64;
    const int r0   = msub * 16 + rl;
    // ldsm lane roles (K-pattern: n-rows, k-split)
    const int ksrow = (lane & 7) + 8 * ((lane >> 4) & 1);
    const int ksk   = 8 * ((lane >> 3) & 1);

    float acc[12][4];
    #pragma unroll
    for (int j = 0; j < 12; j++)
        #pragma unroll
        for (int i = 0; i < 4; i++) acc[j][i] = 0.f;

    for (int k0 = 0; k0 < E_; k0 += 64) {
        __syncthreads();
        #pragma unroll
        for (int i = 0; i < 2; i++) {
            int f = t + 256 * i;               // 0..511
            int r = f >> 3, c8 = (f & 7) * 8;
            const float* xp = x + (size_t)(m0 + r) * E_ + k0 + c8;
            float4 a = *(const float4*)xp;
            float4 b = *(const float4*)(xp + 4);
            uint4 hi, lo;
            split2(a.x, a.y, hi.x, lo.x);
            split2(a.z, a.w, hi.y, lo.y);
            split2(b.x, b.y, hi.z, lo.z);
            split2(b.z, b.w, hi.w, lo.w);
            *(uint4*)&Xh[r*WP + c8] = hi;
            *(uint4*)&Xl[r*WP + c8] = lo;
        }
        #pragma unroll
        for (int i = 0; i < 6; i++) {
            int f = t + 256 * i;               // 0..1535
            int r = f >> 3, c8 = (f & 7) * 8;
            *(uint4*)&Wh[r*WP + c8] = *(const uint4*)&g_wh[(size_t)r * E_ + k0 + c8];
            *(uint4*)&Wl[r*WP + c8] = *(const uint4*)&g_wl[(size_t)r * E_ + k0 + c8];
        }
        __syncthreads();

        #pragma unroll
        for (int kk = 0; kk < 4; kk++) {
            int kb = kk * 16 + kq;
            uint32_t Ah[4], Al[4];
            Ah[0] = *(const uint32_t*)&Xh[(r0  )*WP + kb  ];
            Ah[1] = *(const uint32_t*)&Xh[(r0+8)*WP + kb  ];
            Ah[2] = *(const uint32_t*)&Xh[(r0  )*WP + kb+8];
            Ah[3] = *(const uint32_t*)&Xh[(r0+8)*WP + kb+8];
            Al[0] = *(const uint32_t*)&Xl[(r0  )*WP + kb  ];
            Al[1] = *(const uint32_t*)&Xl[(r0+8)*WP + kb  ];
            Al[2] = *(const uint32_t*)&Xl[(r0  )*WP + kb+8];
            Al[3] = *(const uint32_t*)&Xl[(r0+8)*WP + kb+8];
            uint32_t Bh[12][2], Bl[12][2];
            #pragma unroll
            for (int p = 0; p < 6; p++) {
                int rowbase = nhalf*96 + 16*p + ksrow;
                ldsm4(Bh[2*p][0], Bh[2*p][1], Bh[2*p+1][0], Bh[2*p+1][1],
                      &Wh[rowbase*WP + kk*16 + ksk]);
                ldsm4(Bl[2*p][0], Bl[2*p][1], Bl[2*p+1][0], Bl[2*p+1][1],
                      &Wl[rowbase*WP + kk*16 + ksk]);
            }
            #pragma unroll
            for (int j = 0; j < 12; j++) mma_bf16(acc[j], Ah, Bh[j]);
            #pragma unroll
            for (int j = 0; j < 12; j++) mma_bf16(acc[j], Ah, Bl[j]);
            #pragma unroll
            for (int j = 0; j < 12; j++) mma_bf16(acc[j], Al, Bh[j]);
        }
    }

    const float* bs[3] = {bq, bk, bv};
    __nv_bfloat16* oh[3] = {g_qh, g_kh, g_vh};
    __nv_bfloat16* ol[3] = {g_ql, g_kl, g_vl};
    #pragma unroll
    for (int j = 0; j < 12; j++) {
        int gn = nhalf*12 + j;
        int ct = gn * 8 + kq;
        int mat = ct >> 6, cl = ct & 63;
        float sc = (mat == 0) ? 0.125f : 1.0f;
        float b0 = bs[mat][cl], b1 = bs[mat][cl+1];
        size_t row = (size_t)(m0 + r0);
        uint32_t h0, l0, h1, l1;
        split2((acc[j][0] + b0) * sc, (acc[j][1] + b1) * sc, h0, l0);
        split2((acc[j][2] + b0) * sc, (acc[j][3] + b1) * sc, h1, l1);
        *(uint32_t*)&oh[mat][ row      * H_ + cl] = h0;
        *(uint32_t*)&ol[mat][ row      * H_ + cl] = l0;
        *(uint32_t*)&oh[mat][(row + 8) * H_ + cl] = h1;
        *(uint32_t*)&ol[mat][(row + 8) * H_ + cl] = l1;
    }
}

// ---------------------------------------------------------------------------
// fa: 256 threads = 2 warp-groups; group g handles kt = g, g+2, ...
// K B-frags via ldmatrix; V B-frags via ldmatrix.trans (no transpose stores).
// ---------------------------------------------------------------------------
__global__ __launch_bounds__(256) void fa_mma(float* __restrict__ Y)
{
    extern __shared__ __align__(16) __nv_bfloat16 fsm[];
    __nv_bfloat16* Qh = fsm;                       // [64][WP]
    __nv_bfloat16* Ql = fsm + 4608;

    const int b    = blockIdx.y;
    const int qt   = 31 - blockIdx.x;              // heavy tiles first
    const int t    = threadIdx.x;
    const int w    = t >> 5;
    const int lane = t & 31;
    const int rl   = lane >> 2;
    const int cq   = (lane & 3) * 2;
    const int g    = w >> 2;                       // warp group 0/1
    const int qrow = (w & 3) * 16 + rl;
    const int gt   = t & 127;
    // ldsm lane roles
    const int ksrow = (lane & 7) + 8 * ((lane >> 4) & 1);  // K: n-row in 16-block
    const int ksk   = 8 * ((lane >> 3) & 1);               // K: k-half
    const int vsrow = (lane & 7) + 8 * ((lane >> 3) & 1);  // V: kv-row in 16-block
    const int vsh   = 8 * ((lane >> 4) & 1);               // V: h-half

    __nv_bfloat16* Kh = fsm + 9216 + g * 18432;
    __nv_bfloat16* Kl = Kh + 4608;
    __nv_bfloat16* Vh = Kh + 9216;
    __nv_bfloat16* Vl = Kh + 13824;

    const size_t qbase  = (size_t)(b * S_ + qt * 64);
    const size_t kvbase = (size_t)b * S_;

    #pragma unroll
    for (int i = 0; i < 2; i++) {
        int f = t + 256 * i;                 // 0..511
        int r = f >> 3, c8 = (f & 7) * 8;
        *(uint4*)&Qh[r*WP + c8] = *(const uint4*)&g_qh[(qbase + r) * H_ + c8];
        *(uint4*)&Ql[r*WP + c8] = *(const uint4*)&g_ql[(qbase + r) * H_ + c8];
    }
    __syncthreads();

    uint32_t QAh[4][4], QAl[4][4];
    #pragma unroll
    for (int kk = 0; kk < 4; kk++) {
        int kb = kk * 16 + cq;
        QAh[kk][0] = *(const uint32_t*)&Qh[(qrow  )*WP + kb  ];
        QAh[kk][1] = *(const uint32_t*)&Qh[(qrow+8)*WP + kb  ];
        QAh[kk][2] = *(const uint32_t*)&Qh[(qrow  )*WP + kb+8];
        QAh[kk][3] = *(const uint32_t*)&Qh[(qrow+8)*WP + kb+8];
        QAl[kk][0] = *(const uint32_t*)&Ql[(qrow  )*WP + kb  ];
        QAl[kk][1] = *(const uint32_t*)&Ql[(qrow+8)*WP + kb  ];
        QAl[kk][2] = *(const uint32_t*)&Ql[(qrow  )*WP + kb+8];
        QAl[kk][3] = *(const uint32_t*)&Ql[(qrow+8)*WP + kb+8];
    }

    float o[8][4];
    #pragma unroll
    for (int j = 0; j < 8; j++)
        #pragma unroll
        for (int i = 0; i < 4; i++) o[j][i] = 0.f;
    float mrow[2] = {-1e30f, -1e30f};
    float lrow[2] = {0.f, 0.f};

    for (int kt = g; kt <= qt; kt += 2) {
        asm volatile("bar.sync %0, 128;" :: "r"(1 + g) : "memory");
        #pragma unroll
        for (int i = 0; i < 4; i++) {
            int f = gt + 128 * i;            // 0..511
            int r = f >> 3, c8 = (f & 7) * 8;
            size_t gi = (kvbase + kt * 64 + r) * H_ + c8;
            *(uint4*)&Kh[r*WP + c8] = *(const uint4*)&g_kh[gi];
            *(uint4*)&Kl[r*WP + c8] = *(const uint4*)&g_kl[gi];
            *(uint4*)&Vh[r*WP + c8] = *(const uint4*)&g_vh[gi];
            *(uint4*)&Vl[r*WP + c8] = *(const uint4*)&g_vl[gi];
        }
        asm volatile("bar.sync %0, 128;" :: "r"(1 + g) : "memory");

        // ---- S = Qs @ K^T ----
        float s[8][4];
        #pragma unroll
        for (int j = 0; j < 8; j++)
            #pragma unroll
            for (int i = 0; i < 4; i++) s[j][i] = 0.f;

        #pragma unroll
        for (int kk = 0; kk < 4; kk++) {
            uint32_t Bh[8][2], Bl[8][2];
            #pragma unroll
            for (int p = 0; p < 4; p++) {
                ldsm4(Bh[2*p][0], Bh[2*p][1], Bh[2*p+1][0], Bh[2*p+1][1],
                      &Kh[(16*p + ksrow)*WP + kk*16 + ksk]);
                ldsm4(Bl[2*p][0], Bl[2*p][1], Bl[2*p+1][0], Bl[2*p+1][1],
                      &Kl[(16*p + ksrow)*WP + kk*16 + ksk]);
            }
            #pragma unroll
            for (int j = 0; j < 8; j++) mma_bf16(s[j], QAh[kk], Bh[j]);
            #pragma unroll
            for (int j = 0; j < 8; j++) mma_bf16(s[j], QAh[kk], Bl[j]);
            #pragma unroll
            for (int j = 0; j < 8; j++) mma_bf16(s[j], QAl[kk], Bh[j]);
        }

        if (kt == qt) {
            #pragma unroll
            for (int j = 0; j < 8; j++) {
                int c0 = j * 8 + cq;
                if (c0     > qrow)     s[j][0] = -1e30f;
                if (c0 + 1 > qrow)     s[j][1] = -1e30f;
                if (c0     > qrow + 8) s[j][2] = -1e30f;
                if (c0 + 1 > qrow + 8) s[j][3] = -1e30f;
            }
        }

        // ---- online softmax ----
        float mx0 = -1e30f, mx1 = -1e30f;
        #pragma unroll
        for (int j = 0; j < 8; j++) {
            mx0 = fmaxf(mx0, fmaxf(s[j][0], s[j][1]));
            mx1 = fmaxf(mx1, fmaxf(s[j][2], s[j][3]));
        }
        mx0 = fmaxf(mx0, __shfl_xor_sync(0xffffffffu, mx0, 1));
        mx0 = fmaxf(mx0, __shfl_xor_sync(0xffffffffu, mx0, 2));
        mx1 = fmaxf(mx1, __shfl_xor_sync(0xffffffffu, mx1, 1));
        mx1 = fmaxf(mx1, __shfl_xor_sync(0xffffffffu, mx1, 2));

        float mn0 = fmaxf(mrow[0], mx0), mn1 = fmaxf(mrow[1], mx1);
        float corr0 = __expf(mrow[0] - mn0), corr1 = __expf(mrow[1] - mn1);
        mrow[0] = mn0; mrow[1] = mn1;

        float sum0 = 0.f, sum1 = 0.f;
        #pragma unroll
        for (int j = 0; j < 8; j++) {
            s[j][0] = __expf(s[j][0] - mn0);
            s[j][1] = __expf(s[j][1] - mn0);
            s[j][2] = __expf(s[j][2] - mn1);
            s[j][3] = __expf(s[j][3] - mn1);
            sum0 += s[j][0] + s[j][1];
            sum1 += s[j][2] + s[j][3];
        }
        sum0 += __shfl_xor_sync(0xffffffffu, sum0, 1);
        sum0 += __shfl_xor_sync(0xffffffffu, sum0, 2);
        sum1 += __shfl_xor_sync(0xffffffffu, sum1, 1);
        sum1 += __shfl_xor_sync(0xffffffffu, sum1, 2);
        lrow[0] = lrow[0] * corr0 + sum0;
        lrow[1] = lrow[1] * corr1 + sum1;

        #pragma unroll
        for (int j = 0; j < 8; j++) {
            o[j][0] *= corr0; o[j][1] *= corr0;
            o[j][2] *= corr1; o[j][3] *= corr1;
        }

        // ---- P frags (hi/lo) in regs ----
        uint32_t Ph[4][4], Pl[4][4];
        #pragma unroll
        for (int kk = 0; kk < 4; kk++) {
            #pragma unroll
            for (int half = 0; half < 2; half++) {
                int jj = 2*kk + half;
                split2(s[jj][0], s[jj][1], Ph[kk][half*2+0], Pl[kk][half*2+0]);
                split2(s[jj][2], s[jj][3], Ph[kk][half*2+1], Pl[kk][half*2+1]);
            }
        }

        // ---- O += P @ V ----
        #pragma unroll
        for (int kk = 0; kk < 4; kk++) {
            uint32_t Bh[8][2], Bl[8][2];
            #pragma unroll
            for (int p = 0; p < 4; p++) {
                ldsm4t(Bh[2*p][0], Bh[2*p][1], Bh[2*p+1][0], Bh[2*p+1][1],
                       &Vh[(kk*16 + vsrow)*WP + 16*p + vsh]);
                ldsm4t(Bl[2*p][0], Bl[2*p][1], Bl[2*p+1][0], Bl[2*p+1][1],
                       &Vl[(kk*16 + vsrow)*WP + 16*p + vsh]);
            }
            #pragma unroll
            for (int jh = 0; jh < 8; jh++) mma_bf16(o[jh], Ph[kk], Bh[jh]);
            #pragma unroll
            for (int jh = 0; jh < 8; jh++) mma_bf16(o[jh], Ph[kk], Bl[jh]);
            #pragma unroll
            for (int jh = 0; jh < 8; jh++) mma_bf16(o[jh], Pl[kk], Bh[jh]);
        }
    }

    // ---- merge the two groups' partial states ----
    float* mbuf = (float*)((char*)fsm + 55296);   // inside group-1 KV region; stride 37
    if (g == 1) {
        float* p = mbuf + gt * 37;
        p[0] = mrow[0]; p[1] = mrow[1]; p[2] = lrow[0]; p[3] = lrow[1];
        #pragma unroll
        for (int j = 0; j < 8; j++)
            #pragma unroll
            for (int i = 0; i < 4; i++) p[4 + j*4 + i] = o[j][i];
    }
    __syncthreads();
    if (g == 0) {
        const float* p = mbuf + gt * 37;
        float m1a = p[0], m1b = p[1], l1a = p[2], l1b = p[3];
        float mA = fmaxf(mrow[0], m1a), mB = fmaxf(mrow[1], m1b);
        float w0a = __expf(mrow[0] - mA), w1a = __expf(m1a - mA);
        float w0b = __expf(mrow[1] - mB), w1b = __expf(m1b - mB);
        float invA = 1.0f / (lrow[0] * w0a + l1a * w1a);
        float invB = 1.0f / (lrow[1] * w0b + l1b * w1b);
        float* Yb = Y + qbase * H_;
        #pragma unroll
        for (int j = 0; j < 8; j++) {
            int col = j * 8 + cq;
            float oa0 = (o[j][0] * w0a + p[4 + j*4 + 0] * w1a) * invA;
            float oa1 = (o[j][1] * w0a + p[4 + j*4 + 1] * w1a) * invA;
            float ob0 = (o[j][2] * w0b + p[4 + j*4 + 2] * w1b) * invB;
            float ob1 = (o[j][3] * w0b + p[4 + j*4 + 3] * w1b) * invB;
            *(float2*)(Yb + (size_t)(qrow    ) * H_ + col) = make_float2(oa0, oa1);
            *(float2*)(Yb + (size_t)(qrow + 8) * H_ + col) = make_float2(ob0, ob1);
        }
    }
}

// ---------------------------------------------------------------------------
extern "C" void kernel_launch(void* const* d_in, const int* in_sizes, int n_in,
                              void* d_out, int out_size)
{
    const float* x  = (const float*)d_in[0];
    const float* wq = (const float*)d_in[1];
    const float* bq = (const float*)d_in[2];
    const float* wk = (const float*)d_in[3];
    const float* bk = (const float*)d_in[4];
    const float* wv = (const float*)d_in[5];
    const float* bv = (const float*)d_in[6];
    float* y = (float*)d_out;

    convert_w<<<dim3(16, 3), 256>>>(wq, wk, wv);

    const int qsh = (4608*2 + 13824*2) * (int)sizeof(__nv_bfloat16);  // 73728
    cudaFuncSetAttribute(qkv_mma, cudaFuncAttributeMaxDynamicSharedMemorySize, qsh);
    qkv_mma<<<M_/64, 256, qsh>>>(x, bq, bk, bv);

    const int fsh = (9216 + 2*18432) * (int)sizeof(__nv_bfloat16);    // 92160
    cudaFuncSetAttribute(fa_mma, cudaFuncAttributeMaxDynamicSharedMemorySize, fsh);
    fa_mma<<<dim3(32, B_), 256, fsh>>>(y);
}